// round 15
// baseline (speedup 1.0000x reference)
#include <cuda_runtime.h>
#include <cuda_bf16.h>
#include <cstdint>

#define BSZ 16
#define TOK 784
#define CH  768
#define NCLS 200
#define LDL 192          // logits row stride (main cols only; tail fused)
#define XN  (BSZ * TOK)  // 12544 rows

// ---------------- scratch (device globals; no allocations allowed) ----------
__device__ float g_logits[XN * LDL];           // 9.6 MB
__device__ float g_mlog[XN];
__device__ int   g_sel[BSZ];
__device__ float g_ym[576 * 192];              // (b,6x6) @ W_m^T + b_m
__device__ float g_ys[256 * 384];              // (b,4x4) @ W_s^T + b_s
__device__ __nv_bfloat16 g_xhi[XN * CH];       // 19.3 MB
__device__ __nv_bfloat16 g_xlo[XN * CH];       // 19.3 MB
__device__ __nv_bfloat16 g_whi[192 * CH];
__device__ __nv_bfloat16 g_wlo[192 * CH];

static __device__ __forceinline__ unsigned smaddr(const void* p) {
    return (unsigned)__cvta_generic_to_shared(p);
}

// ===== split x and W_fc[0:192] into bf16 hi/lo ==============================
// grid = 9552: blocks [0,9408) cover x (float4 each thread), rest cover W.
__global__ __launch_bounds__(256) void cvt_split_kernel(
    const float* __restrict__ x, const float* __restrict__ W_fc)
{
    int bid = blockIdx.x, tid = threadIdx.x;
    const float* src; __nv_bfloat16 *dhi, *dlo; size_t i;
    if (bid < 9408) { i = (size_t)bid * 256 + tid; src = x;    dhi = g_xhi; dlo = g_xlo; }
    else            { i = (size_t)(bid - 9408) * 256 + tid; src = W_fc; dhi = g_whi; dlo = g_wlo; }
    float4 v = *(const float4*)(src + i * 4);
    __nv_bfloat16 h0 = __float2bfloat16_rn(v.x), h1 = __float2bfloat16_rn(v.y);
    __nv_bfloat16 h2 = __float2bfloat16_rn(v.z), h3 = __float2bfloat16_rn(v.w);
    __nv_bfloat16 l0 = __float2bfloat16_rn(v.x - __bfloat162float(h0));
    __nv_bfloat16 l1 = __float2bfloat16_rn(v.y - __bfloat162float(h1));
    __nv_bfloat16 l2 = __float2bfloat16_rn(v.z - __bfloat162float(h2));
    __nv_bfloat16 l3 = __float2bfloat16_rn(v.w - __bfloat162float(h3));
    __nv_bfloat162 ph01{h0, h1}, ph23{h2, h3}, pl01{l0, l1}, pl23{l2, l3};
    uint2 uh{*(unsigned*)&ph01, *(unsigned*)&ph23};
    uint2 ul{*(unsigned*)&pl01, *(unsigned*)&pl23};
    *reinterpret_cast<uint2*>(dhi + i * 4) = uh;
    *reinterpret_cast<uint2*>(dlo + i * 4) = ul;
}

// ===== fc GEMM via bf16-split tensor cores ==================================
// logits[m, bn+n] = sum_k x[m,k]*W[n',k] + bias, n' = bn+n, via
// hi*hi + hi*lo + lo*hi mma accumulation (~fp32 accuracy).
// grid (3, 98), block 256 = 8 warps (4 in M x 2 in N); warp tile 32x32.
__global__ __launch_bounds__(256) void gemm_fc_mma(const float* __restrict__ bias)
{
    __shared__ __align__(16) __nv_bfloat16 Ah[2][128][24];
    __shared__ __align__(16) __nv_bfloat16 Al[2][128][24];
    __shared__ __align__(16) __nv_bfloat16 Bh[2][64][24];
    __shared__ __align__(16) __nv_bfloat16 Bl[2][64][24];

    const int tid = threadIdx.x, lane = tid & 31, wid = tid >> 5;
    const int warpm = wid & 3, warpn = wid >> 2;
    const int bm = blockIdx.y * 128, bn = blockIdx.x * 64;

    // loaders
    const int arow = tid >> 1, acol = (tid & 1) << 3;        // 128 x 16, 8 bf16/thr
    const int brow = tid >> 2, bcol = (tid & 3) << 2;        // 64 x 16, 4 bf16/thr
    const __nv_bfloat16* gah = g_xhi + (size_t)(bm + arow) * CH + acol;
    const __nv_bfloat16* gal = g_xlo + (size_t)(bm + arow) * CH + acol;
    const __nv_bfloat16* gbh = g_whi + (size_t)(bn + brow) * CH + bcol;
    const __nv_bfloat16* gbl = g_wlo + (size_t)(bn + brow) * CH + bcol;

    {   // preload chunk 0
        uint4 vh = *(const uint4*)gah, vl = *(const uint4*)gal;
        uint2 wh = *(const uint2*)gbh, wl = *(const uint2*)gbl;
        *(uint4*)&Ah[0][arow][acol] = vh;
        *(uint4*)&Al[0][arow][acol] = vl;
        *(uint2*)&Bh[0][brow][bcol] = wh;
        *(uint2*)&Bl[0][brow][bcol] = wl;
    }
    __syncthreads();

    float acc[2][4][4];
#pragma unroll
    for (int mg = 0; mg < 2; mg++)
#pragma unroll
        for (int ng = 0; ng < 4; ng++)
#pragma unroll
            for (int j = 0; j < 4; j++) acc[mg][ng][j] = 0.f;

    // ldmatrix element offsets (within one [rows][24] buffer), bytes
    const unsigned aoff = ((warpm * 32 + (lane & 15)) * 24 + ((lane >> 4) << 3)) * 2;
    const unsigned boff = ((warpn * 32 + (lane & 7)) * 24 + (((lane >> 3) & 1) << 3)) * 2;
    const unsigned ahb0 = smaddr(&Ah[0][0][0]), ahb1 = smaddr(&Ah[1][0][0]);
    const unsigned alb0 = smaddr(&Al[0][0][0]), alb1 = smaddr(&Al[1][0][0]);
    const unsigned bhb0 = smaddr(&Bh[0][0][0]), bhb1 = smaddr(&Bh[1][0][0]);
    const unsigned blb0 = smaddr(&Bl[0][0][0]), blb1 = smaddr(&Bl[1][0][0]);

    const int NIT = CH >> 4;              // 48
    for (int it = 0; it < NIT; it++) {
        const int cur = it & 1;
        const bool more = (it + 1 < NIT);
        uint4 nvh, nvl; uint2 nwh, nwl;
        if (more) {
            int k0 = (it + 1) << 4;
            nvh = *(const uint4*)(gah + k0);
            nvl = *(const uint4*)(gal + k0);
            nwh = *(const uint2*)(gbh + k0);
            nwl = *(const uint2*)(gbl + k0);
        }

        const unsigned ah = cur ? ahb1 : ahb0;
        const unsigned al = cur ? alb1 : alb0;
        const unsigned bh = cur ? bhb1 : bhb0;
        const unsigned bl = cur ? blb1 : blb0;

        unsigned afh[2][4], afl[2][4];
#pragma unroll
        for (int mg = 0; mg < 2; mg++) {
            unsigned addr = ah + aoff + mg * 768;   // mg*16 rows * 48B
            asm volatile("ldmatrix.sync.aligned.m8n8.x4.shared.b16 {%0,%1,%2,%3}, [%4];"
                         : "=r"(afh[mg][0]), "=r"(afh[mg][1]), "=r"(afh[mg][2]), "=r"(afh[mg][3])
                         : "r"(addr));
            addr = al + aoff + mg * 768;
            asm volatile("ldmatrix.sync.aligned.m8n8.x4.shared.b16 {%0,%1,%2,%3}, [%4];"
                         : "=r"(afl[mg][0]), "=r"(afl[mg][1]), "=r"(afl[mg][2]), "=r"(afl[mg][3])
                         : "r"(addr));
        }
#pragma unroll
        for (int ng = 0; ng < 4; ng++) {
            unsigned bfh0, bfh1, bfl0, bfl1;
            unsigned addr = bh + boff + ng * 384;   // ng*8 rows * 48B
            asm volatile("ldmatrix.sync.aligned.m8n8.x2.shared.b16 {%0,%1}, [%2];"
                         : "=r"(bfh0), "=r"(bfh1) : "r"(addr));
            addr = bl + boff + ng * 384;
            asm volatile("ldmatrix.sync.aligned.m8n8.x2.shared.b16 {%0,%1}, [%2];"
                         : "=r"(bfl0), "=r"(bfl1) : "r"(addr));
#pragma unroll
            for (int mg = 0; mg < 2; mg++) {
                float* c = acc[mg][ng];
                asm volatile("mma.sync.aligned.m16n8k16.row.col.f32.bf16.bf16.f32 "
                             "{%0,%1,%2,%3}, {%4,%5,%6,%7}, {%8,%9}, {%0,%1,%2,%3};"
                             : "+f"(c[0]), "+f"(c[1]), "+f"(c[2]), "+f"(c[3])
                             : "r"(afh[mg][0]), "r"(afh[mg][1]), "r"(afh[mg][2]), "r"(afh[mg][3]),
                               "r"(bfh0), "r"(bfh1));
                asm volatile("mma.sync.aligned.m16n8k16.row.col.f32.bf16.bf16.f32 "
                             "{%0,%1,%2,%3}, {%4,%5,%6,%7}, {%8,%9}, {%0,%1,%2,%3};"
                             : "+f"(c[0]), "+f"(c[1]), "+f"(c[2]), "+f"(c[3])
                             : "r"(afh[mg][0]), "r"(afh[mg][1]), "r"(afh[mg][2]), "r"(afh[mg][3]),
                               "r"(bfl0), "r"(bfl1));
                asm volatile("mma.sync.aligned.m16n8k16.row.col.f32.bf16.bf16.f32 "
                             "{%0,%1,%2,%3}, {%4,%5,%6,%7}, {%8,%9}, {%0,%1,%2,%3};"
                             : "+f"(c[0]), "+f"(c[1]), "+f"(c[2]), "+f"(c[3])
                             : "r"(afl[mg][0]), "r"(afl[mg][1]), "r"(afl[mg][2]), "r"(afl[mg][3]),
                               "r"(bfh0), "r"(bfh1));
            }
        }

        if (more) {
            const int nxt = cur ^ 1;      // safe: it-1's barrier drained reads
            *(uint4*)&Ah[nxt][arow][acol] = nvh;
            *(uint4*)&Al[nxt][arow][acol] = nvl;
            *(uint2*)&Bh[nxt][brow][bcol] = nwh;
            *(uint2*)&Bl[nxt][brow][bcol] = nwl;
            __syncthreads();
        }
    }

    // epilogue: c0,c1 at (row, col..col+1); c2,c3 at (row+8, same cols)
#pragma unroll
    for (int mg = 0; mg < 2; mg++)
#pragma unroll
        for (int ng = 0; ng < 4; ng++) {
            float* c = acc[mg][ng];
            int m  = bm + warpm * 32 + mg * 16 + (lane >> 2);
            int nl = warpn * 32 + ng * 8 + ((lane & 3) << 1);
            float b0 = bias[bn + nl], b1 = bias[bn + nl + 1];
            float2 v0 = make_float2(c[0] + b0, c[1] + b1);
            float2 v1 = make_float2(c[2] + b0, c[3] + b1);
            *(float2*)(g_logits + (size_t)m * LDL + bn + nl) = v0;
            *(float2*)(g_logits + (size_t)(m + 8) * LDL + bn + nl) = v1;
        }
}

// ===== fused: fc tail cols [192,200) + per-token max(softmax) ==============
__global__ __launch_bounds__(256) void softmax_tail_kernel(
    const float* __restrict__ x, const float* __restrict__ W_fc,
    const float* __restrict__ b_fc)
{
    __shared__ float Ws[8 * CH];     // W_fc rows 192..199, 24 KB
    __shared__ float bs[8];
    const int tid = threadIdx.x;
#pragma unroll
    for (int i = 0; i < 6; i++) {
        int idx = i * 256 + tid;                     // 0..1535
        ((float4*)Ws)[idx] = *(const float4*)(W_fc + (size_t)192 * CH + idx * 4);
    }
    if (tid < 8) bs[tid] = b_fc[192 + tid];
    __syncthreads();

    const int warp = tid >> 5, lane = tid & 31;
    const int t = blockIdx.x * 8 + warp;             // token; grid covers 12544
    const float4* xr = (const float4*)(x + (size_t)t * CH);

    float4 xv[6];
#pragma unroll
    for (int i = 0; i < 6; i++) xv[i] = xr[lane + 32 * i];

    float tail[8];
#pragma unroll
    for (int n = 0; n < 8; n++) {
        const float4* wr = (const float4*)(Ws + n * CH);
        float s = 0.f;
#pragma unroll
        for (int i = 0; i < 6; i++) {
            float4 w = wr[lane + 32 * i];
            s += xv[i].x * w.x + xv[i].y * w.y + xv[i].z * w.z + xv[i].w * w.w;
        }
#pragma unroll
        for (int o = 16; o; o >>= 1) s += __shfl_xor_sync(0xffffffffu, s, o);
        tail[n] = s + bs[n];
    }

    const float* row = g_logits + (size_t)t * LDL;
    float lv[6];
#pragma unroll
    for (int i = 0; i < 6; i++) lv[i] = row[lane + 32 * i];

    float m = -1e30f;
#pragma unroll
    for (int i = 0; i < 6; i++) m = fmaxf(m, lv[i]);
#pragma unroll
    for (int n = 0; n < 8; n++) m = fmaxf(m, tail[n]);
#pragma unroll
    for (int o = 16; o; o >>= 1) m = fmaxf(m, __shfl_xor_sync(0xffffffffu, m, o));

    float s = 0.f;
#pragma unroll
    for (int i = 0; i < 6; i++) s += __expf(lv[i] - m);
    if (lane < 8) s += __expf(tail[lane] - m);
#pragma unroll
    for (int o = 16; o; o >>= 1) s += __shfl_xor_sync(0xffffffffu, s, o);
    if (lane == 0) g_mlog[t] = 1.0f / s;
}

// ------- window-mean (8x8, stride 3, pad 2) * mask -> argmax over 81 --------
__global__ void select_kernel(const float* __restrict__ mask)
{
    __shared__ float vals[81];
    int b = blockIdx.x;
    int p = threadIdx.x;
    if (p < 81) {
        int pr = p / 9, pc = p % 9;
        float s = 0.f;
        for (int ki = 0; ki < 8; ki++) {
            int fi = pr * 3 + ki - 2;
            if (fi < 0 || fi >= 28) continue;
            for (int kj = 0; kj < 8; kj++) {
                int fj = pc * 3 + kj - 2;
                if (fj < 0 || fj >= 28) continue;
                s += g_mlog[b * TOK + fi * 28 + fj];
            }
        }
        vals[p] = (s * (1.0f / 64.0f)) * mask[b * 81 + p];
    }
    __syncthreads();
    if (p == 0) {
        float best = vals[0]; int bi = 0;
        for (int i = 1; i < 81; i++)
            if (vals[i] > best) { best = vals[i]; bi = i; }
        g_sel[b] = bi;
    }
}

// ===== fused parts GEMM (double-buffered) + image resize, one wave =========
__global__ __launch_bounds__(256) void fused_parts_image(
    const float* __restrict__ x,
    const float* __restrict__ W_l, const float* __restrict__ b_l,
    const float* __restrict__ W_m, const float* __restrict__ b_m,
    const float* __restrict__ W_s, const float* __restrict__ b_s,
    const float* __restrict__ img,
    float* __restrict__ out)
{
    const int tid = threadIdx.x;
    const int bid = blockIdx.x;

    if (bid >= 99) {
        // ----- image resize path (49 blocks, grid-stride) -----
        const int TOTAL = BSZ * 3 * 224 * 224;
        const int stride = 49 * 256;
        float* iout = out + (size_t)BSZ * 64 * CH;
        for (int idx = (bid - 99) * 256 + tid; idx < TOTAL; idx += stride) {
            int xo = idx % 224;
            int y  = (idx / 224) % 224;
            int ch = (idx / (224 * 224)) % 3;
            int b  = idx / (224 * 224 * 3);
            int p = g_sel[b]; int pr = p / 9, pc = p % 9;

            const float S = 4.0f / 7.0f;
            float sy = fminf(fmaxf((y + 0.5f) * S - 0.5f, 0.f), 127.f);
            float sx = fminf(fmaxf((xo + 0.5f) * S - 0.5f, 0.f), 127.f);
            int y0 = (int)sy; float fy = sy - (float)y0; int y1 = min(y0 + 1, 127);
            int x0 = (int)sx; float fx = sx - (float)x0; int x1 = min(x0 + 1, 127);

            const float* ib = img + ((size_t)b * 3 + ch) * 448 * 448;
            int gy0 = pr * 48 + y0 - 32, gy1 = pr * 48 + y1 - 32;
            int gx0 = pc * 48 + x0 - 32, gx1 = pc * 48 + x1 - 32;
            bool vy0 = (gy0 >= 0 && gy0 < 448), vy1 = (gy1 >= 0 && gy1 < 448);
            bool vx0 = (gx0 >= 0 && gx0 < 448), vx1 = (gx1 >= 0 && gx1 < 448);
            float v00 = (vy0 && vx0) ? ib[gy0 * 448 + gx0] : 0.f;
            float v01 = (vy0 && vx1) ? ib[gy0 * 448 + gx1] : 0.f;
            float v10 = (vy1 && vx0) ? ib[gy1 * 448 + gx0] : 0.f;
            float v11 = (vy1 && vx1) ? ib[gy1 * 448 + gx1] : 0.f;
            iout[idx] = (1.f - fy) * ((1.f - fx) * v00 + fx * v01)
                      + fy * ((1.f - fx) * v10 + fx * v11);
        }
        return;
    }

    // ----- parts GEMM path (99 blocks, 64x64 tiles, double-buffered) -----
    __shared__ float As[2][16][64];
    __shared__ float Bs[2][16][64];

    int seg, bm, bn;
    const float *W, *bias;
    if (bid < 48)      { seg = 0; bn = bid % 3;  bm = bid / 3;  W = W_l; bias = b_l; }
    else if (bid < 75) { seg = 1; int t = bid - 48; bn = t % 3; bm = t / 3; W = W_m; bias = b_m; }
    else               { seg = 2; int t = bid - 75; bn = t % 6; bm = t / 6; W = W_s; bias = b_s; }

    const int lr = tid >> 2;
    const int lc = (tid & 3) << 2;

    int gr = bm * 64 + lr;
    int b, y, xx;
    if (seg == 0)      { b = gr >> 6; int i = gr & 63;  y = i >> 3;        xx = i & 7; }
    else if (seg == 1) { b = gr / 36; int i = gr % 36;  y = i / 6 + 1;     xx = i % 6 + 1; }
    else               { b = gr / 16; int i = gr % 16;  y = (i >> 2) + 2;  xx = (i & 3) + 2; }
    int p = g_sel[b];
    int fi = (p / 9) * 3 + y - 2;
    int fj = (p % 9) * 3 + xx - 2;
    const bool avalid = (fi >= 0 && fi < 28 && fj >= 0 && fj < 28);
    const float* Aptr = x + (avalid ? ((size_t)(b * TOK + fi * 28 + fj)) * CH : 0) + lc;
    const float* Wptr = W + (size_t)(bn * 64 + lr) * CH + lc;

    const int tx = tid & 15;
    const int ty = tid >> 4;
    float acc[4][4];
#pragma unroll
    for (int i = 0; i < 4; i++)
#pragma unroll
        for (int j = 0; j < 4; j++) acc[i][j] = 0.f;

    {   // preload chunk 0
        float4 av = make_float4(0.f, 0.f, 0.f, 0.f);
        if (avalid) av = *(const float4*)(Aptr);
        float4 bv = *(const float4*)(Wptr);
        As[0][lc + 0][lr] = av.x; As[0][lc + 1][lr] = av.y;
        As[0][lc + 2][lr] = av.z; As[0][lc + 3][lr] = av.w;
        Bs[0][lc + 0][lr] = bv.x; Bs[0][lc + 1][lr] = bv.y;
        Bs[0][lc + 2][lr] = bv.z; Bs[0][lc + 3][lr] = bv.w;
    }
    __syncthreads();

    const int NIT = CH >> 4;              // 48
    for (int it = 0; it < NIT; it++) {
        const int cur = it & 1;
        const bool more = (it + 1 < NIT);
        float4 nav = make_float4(0.f, 0.f, 0.f, 0.f), nbv;
        if (more) {
            int k0 = (it + 1) << 4;
            if (avalid) nav = *(const float4*)(Aptr + k0);
            nbv = *(const float4*)(Wptr + k0);
        }
#pragma unroll
        for (int k = 0; k < 16; k++) {
            float4 a  = *(const float4*)&As[cur][k][ty << 2];
            float4 bb = *(const float4*)&Bs[cur][k][tx << 2];
            acc[0][0] += a.x * bb.x; acc[0][1] += a.x * bb.y;
            acc[0][2] += a.x * bb.z; acc[0][3] += a.x * bb.w;
            acc[1][0] += a.y * bb.x; acc[1][1] += a.y * bb.y;
            acc[1][2] += a.y * bb.z; acc[1][3] += a.y * bb.w;
            acc[2][0] += a.z * bb.x; acc[2][1] += a.z * bb.y;
            acc[2][2] += a.z * bb.z; acc[2][3] += a.z * bb.w;
            acc[3][0] += a.w * bb.x; acc[3][1] += a.w * bb.y;
            acc[3][2] += a.w * bb.z; acc[3][3] += a.w * bb.w;
        }
        if (more) {
            const int nxt = cur ^ 1;
            As[nxt][lc + 0][lr] = nav.x; As[nxt][lc + 1][lr] = nav.y;
            As[nxt][lc + 2][lr] = nav.z; As[nxt][lc + 3][lr] = nav.w;
            Bs[nxt][lc + 0][lr] = nbv.x; Bs[nxt][lc + 1][lr] = nbv.y;
            Bs[nxt][lc + 2][lr] = nbv.z; Bs[nxt][lc + 3][lr] = nbv.w;
            __syncthreads();
        }
    }

    const int nbase = bn * 64 + (tx << 2);
    const float4 b4 = *(const float4*)(bias + nbase);
#pragma unroll
    for (int i = 0; i < 4; i++) {
        int m = bm * 64 + (ty << 2) + i;
        float4 v = make_float4(acc[i][0] + b4.x, acc[i][1] + b4.y,
                               acc[i][2] + b4.z, acc[i][3] + b4.w);
        if (seg == 0)      *(float4*)(out + (size_t)m * CH + nbase) = v;
        else if (seg == 1) *(float4*)(g_ym + m * 192 + nbase) = v;
        else               *(float4*)(g_ys + m * 384 + nbase) = v;
    }
}

// ===== bilinear upsample Y_m (6x6) and Y_s (4x4) into ff_cat cols ==========
__global__ void interp_ms_kernel(float* __restrict__ out)
{
    int pos = blockIdx.x;   // 0..63
    int b   = blockIdx.y;   // 0..15
    int tid = threadIdx.x;  // 0..383
    int y = pos >> 3, xo = pos & 7;
    float* orow = out + (size_t)(b * 64 + pos) * CH;

    if (tid < 192) {       // m: 6x6 -> 8x8, cols [192,384)
        float sy = fminf(fmaxf(y * 0.75f - 0.125f, 0.f), 5.f);
        float sx = fminf(fmaxf(xo * 0.75f - 0.125f, 0.f), 5.f);
        int y0 = (int)sy; float fy = sy - (float)y0; int y1 = min(y0 + 1, 5);
        int x0 = (int)sx; float fx = sx - (float)x0; int x1 = min(x0 + 1, 5);
        const float* Y = g_ym + (size_t)b * 36 * 192 + tid;
        float v00 = Y[(y0 * 6 + x0) * 192], v01 = Y[(y0 * 6 + x1) * 192];
        float v10 = Y[(y1 * 6 + x0) * 192], v11 = Y[(y1 * 6 + x1) * 192];
        orow[192 + tid] = (1.f - fy) * ((1.f - fx) * v00 + fx * v01)
                        + fy * ((1.f - fx) * v10 + fx * v11);
    }
    {                      // s: 4x4 -> 8x8, cols [384,768)
        float sy = fminf(fmaxf(y * 0.5f - 0.25f, 0.f), 3.f);
        float sx = fminf(fmaxf(xo * 0.5f - 0.25f, 0.f), 3.f);
        int y0 = (int)sy; float fy = sy - (float)y0; int y1 = min(y0 + 1, 3);
        int x0 = (int)sx; float fx = sx - (float)x0; int x1 = min(x0 + 1, 3);
        const float* Y = g_ys + (size_t)b * 16 * 384 + tid;
        float v00 = Y[(y0 * 4 + x0) * 384], v01 = Y[(y0 * 4 + x1) * 384];
        float v10 = Y[(y1 * 4 + x0) * 384], v11 = Y[(y1 * 4 + x1) * 384];
        orow[384 + tid] = (1.f - fy) * ((1.f - fx) * v00 + fx * v01)
                        + fy * ((1.f - fx) * v10 + fx * v11);
    }
}

// ---------------------------------------------------------------------------
extern "C" void kernel_launch(void* const* d_in, const int* in_sizes, int n_in,
                              void* d_out, int out_size)
{
    const float* x    = (const float*)d_in[0];   // [16,784,768]
    const float* mask = (const float*)d_in[1];   // [16,81]
    const float* img  = (const float*)d_in[2];   // [16,3,448,448]
    const float* W_fc = (const float*)d_in[3];   // [200,768]
    const float* b_fc = (const float*)d_in[4];
    const float* W_l  = (const float*)d_in[5];   // [192,768]
    const float* b_l  = (const float*)d_in[6];
    const float* W_m  = (const float*)d_in[7];   // [192,768]
    const float* b_m  = (const float*)d_in[8];
    const float* W_s  = (const float*)d_in[9];   // [384,768]
    const float* b_s  = (const float*)d_in[10];
    float* out = (float*)d_out;

    // 0) split x and W_fc[0:192] into bf16 hi/lo
    cvt_split_kernel<<<9552, 256>>>(x, W_fc);

    // 1) logits cols [0,192) via bf16-split tensor-core mma
    gemm_fc_mma<<<dim3(3, 98), 256>>>(b_fc);

    // 2) fused tail cols [192,200) + max-softmax per token
    softmax_tail_kernel<<<(BSZ * TOK) / 8, 256>>>(x, W_fc, b_fc);

    // 3) masked window-mean argmax -> sel[b]
    select_kernel<<<BSZ, 96>>>(mask);

    // 4) parts GEMMs (double-buffered) + image resize, one 148-block wave
    fused_parts_image<<<148, 256>>>(x, W_l, b_l, W_m, b_m, W_s, b_s, img, out);

    // 5) upsample m/s results into ff_cat cols [192,768)
    interp_ms_kernel<<<dim3(64, BSZ), 384>>>(out);
}